// round 13
// baseline (speedup 1.0000x reference)
#include <cuda_runtime.h>
#include <cuda_bf16.h>
#include <float.h>

#define Bc   8
#define Lc   2048
#define IND  1024
#define Dc   64
#define Hc   2
#define DH   32
#define NNc  32
#define TI   16
#define CANDMAX 288

// scratch (no allocations allowed -> __device__ globals)
__device__ float g_xa[Bc * Lc * Dc];
__device__ float g_xb[Bc * Lc * Dc];
__device__ float g_attn[Bc * Lc * Dc];
__device__ int   g_top[Bc * Lc * NNc];
__device__ float g_norm[Bc * Hc * Lc];
__device__ float g_maxn[2 * Bc * Hc];   // [0..16): layer0, [16..32): layer1

// ---- packed f32x2 helpers (FFMA2) ----
__device__ __forceinline__ void ffma2(unsigned long long& d,
                                      unsigned long long a,
                                      unsigned long long b) {
    asm("fma.rn.f32x2 %0, %1, %2, %0;" : "+l"(d) : "l"(a), "l"(b));
}
__device__ __forceinline__ unsigned long long pk2(float lo, float hi) {
    unsigned long long r;
    asm("mov.b64 %0, {%1, %2};" : "=l"(r) : "f"(lo), "f"(hi));
    return r;
}
__device__ __forceinline__ float upk_sum(unsigned long long v) {
    float lo, hi;
    asm("mov.b64 {%0, %1}, %2;" : "=f"(lo), "=f"(hi) : "l"(v));
    return lo + hi;
}

// ---------------------------------------------------------------------------
// Top-32 smallest dist per row via 256-bucket histogram select (validated).
// ---------------------------------------------------------------------------
__global__ void topk_kernel(const float* __restrict__ dist,
                            const float* __restrict__ mask,
                            int* __restrict__ top) {
    __shared__ int hist[256];
    __shared__ int cum[256];
    __shared__ int wtot[8];
    __shared__ unsigned long long cand[CANDMAX];
    __shared__ int ccount;
    __shared__ int thrB;

    int row = blockIdx.x;
    int b   = row / Lc;
    int t   = threadIdx.x, w = t >> 5, lane = t & 31;
    const float* dr = dist + (size_t)row * Lc;
    const float* mr = mask + b * Lc;

    hist[t] = 0;
    if (t == 0) ccount = 0;
    __syncthreads();

    float v[8]; int bkt[8];
    #pragma unroll
    for (int q = 0; q < 8; q++) {
        int j = w * 256 + q * 32 + lane;
        float m = mr[j];
        float val = (m > 0.f) ? dr[j] : 3.0f;
        v[q] = val;
        int bb = (int)(val * 256.f);
        bb = bb < 0 ? 0 : (bb > 255 ? 255 : bb);
        bkt[q] = bb;
        atomicAdd(&hist[bb], 1);
    }
    __syncthreads();

    {
        int sc = hist[t];
        #pragma unroll
        for (int o = 1; o < 32; o <<= 1) {
            int n = __shfl_up_sync(0xffffffffu, sc, o);
            if (lane >= o) sc += n;
        }
        if (lane == 31) wtot[w] = sc;
        __syncthreads();
        int off = 0;
        #pragma unroll
        for (int k = 0; k < 8; k++) if (k < w) off += wtot[k];
        cum[t] = sc + off;
    }
    __syncthreads();
    if (cum[t] >= NNc && (t == 0 || cum[t - 1] < NNc)) thrB = t;
    __syncthreads();
    int T = thrB;

    #pragma unroll
    for (int q = 0; q < 8; q++) {
        if (bkt[q] <= T) {
            int pos = atomicAdd(&ccount, 1);
            if (pos < CANDMAX) {
                int j = w * 256 + q * 32 + lane;
                cand[pos] = ((unsigned long long)__float_as_uint(v[q]) << 32) | (unsigned)j;
            }
        }
    }
    __syncthreads();
    int C = ccount;

    if (C > CANDMAX) {
        unsigned long long k8[8];
        #pragma unroll
        for (int q = 0; q < 8; q++) {
            int j = w * 256 + q * 32 + lane;
            k8[q] = ((unsigned long long)__float_as_uint(v[q]) << 32) | (unsigned)j;
        }
        for (int k = 0; k < 32; k++) {
            unsigned long long bm = k8[0]; int bq = 0;
            #pragma unroll
            for (int q = 1; q < 8; q++) if (k8[q] < bm) { bm = k8[q]; bq = q; }
            unsigned long long rm = bm;
            #pragma unroll
            for (int o = 16; o; o >>= 1) {
                unsigned long long om = __shfl_xor_sync(0xffffffffu, rm, o);
                rm = om < rm ? om : rm;
            }
            if (bm == rm) k8[bq] = 0xffffffffffffffffull;
            if (lane == 0) cand[w * 32 + k] = rm;
        }
        __syncthreads();
        C = 256;
    }

    for (int c = t; c < C; c += 256) {
        unsigned long long my = cand[c];
        int rank = 0;
        for (int k = 0; k < C; k++) rank += (cand[k] < my);
        if (rank < NNc)
            top[(size_t)row * NNc + rank] = (int)(my & 0xffffffffu);
    }
}

// ---------------------------------------------------------------------------
// Fused front-end MLP (FFMA2 GEMM1); epilogue emits norms.
// ---------------------------------------------------------------------------
__global__ void mlp_kernel(const float* __restrict__ node,
                           const float* __restrict__ gin, const float* __restrict__ bin,
                           const float* __restrict__ w_in, const float* __restrict__ bias_in,
                           const float* __restrict__ g1, const float* __restrict__ b1,
                           const float* __restrict__ w_h, const float* __restrict__ bias_h,
                           const float* __restrict__ g2, const float* __restrict__ b2,
                           float* __restrict__ out,
                           float* __restrict__ nrm, float* __restrict__ mx) {
    __shared__ __align__(16) float xs[8][IND];
    __shared__ float red[4][8][Dc];
    __shared__ float h[8][Dc];
    __shared__ float sn0[8], sn1[8];

    int t = threadIdx.x;
    int w = t >> 5, lane = t & 31;
    size_t row0 = (size_t)blockIdx.x * 8;

    {
        size_t row = row0 + w;
        const float* xr = node + row * IND;
        float vals[IND / 32];
        float s = 0.f;
        #pragma unroll
        for (int k = 0; k < IND / 32; k++) { float v = xr[lane + 32 * k]; vals[k] = v; s += v; }
        #pragma unroll
        for (int o = 16; o; o >>= 1) s += __shfl_xor_sync(0xffffffffu, s, o);
        float mean = s * (1.f / IND);
        float vs = 0.f;
        #pragma unroll
        for (int k = 0; k < IND / 32; k++) { float d = vals[k] - mean; vs += d * d; }
        #pragma unroll
        for (int o = 16; o; o >>= 1) vs += __shfl_xor_sync(0xffffffffu, vs, o);
        float rstd = rsqrtf(vs * (1.f / IND) + 1e-5f);
        #pragma unroll
        for (int k = 0; k < IND / 32; k++) {
            int i = lane + 32 * k;
            xs[w][i] = (vals[k] - mean) * rstd * gin[i] + bin[i];
        }
    }
    __syncthreads();

    {
        int o = t & 63, quad = t >> 6;
        unsigned long long acc[8];
        #pragma unroll
        for (int r = 0; r < 8; r++) acc[r] = pk2(0.f, 0.f);
        int i0 = quad * 256;
        for (int i = i0; i < i0 + 256; i += 4) {
            unsigned long long wp0 = pk2(w_in[(i + 0) * Dc + o], w_in[(i + 1) * Dc + o]);
            unsigned long long wp1 = pk2(w_in[(i + 2) * Dc + o], w_in[(i + 3) * Dc + o]);
            #pragma unroll
            for (int r = 0; r < 8; r++) {
                ulonglong2 xv = *(const ulonglong2*)&xs[r][i];
                ffma2(acc[r], xv.x, wp0);
                ffma2(acc[r], xv.y, wp1);
            }
        }
        #pragma unroll
        for (int r = 0; r < 8; r++) red[quad][r][o] = upk_sum(acc[r]);
    }
    __syncthreads();
    for (int p = t; p < 8 * Dc; p += 256) {
        int r = p >> 6, o = p & 63;
        float v = red[0][r][o] + red[1][r][o] + red[2][r][o] + red[3][r][o] + bias_in[o];
        h[r][o] = v > 0.f ? v : 0.01f * v;
    }
    __syncthreads();

    {
        float a = h[w][lane], c = h[w][lane + 32];
        float s = a + c;
        #pragma unroll
        for (int o = 16; o; o >>= 1) s += __shfl_xor_sync(0xffffffffu, s, o);
        float mean = s * (1.f / 64.f);
        float da = a - mean, dc = c - mean;
        float vv = da * da + dc * dc;
        #pragma unroll
        for (int o = 16; o; o >>= 1) vv += __shfl_xor_sync(0xffffffffu, vv, o);
        float rstd = rsqrtf(vv * (1.f / 64.f) + 1e-5f);
        h[w][lane]      = da * rstd * g1[lane] + b1[lane];
        h[w][lane + 32] = dc * rstd * g1[lane + 32] + b1[lane + 32];
    }
    __syncthreads();

    float h2tmp[2];
    #pragma unroll
    for (int pp = 0; pp < 2; pp++) {
        int p = t + pp * 256;
        int r = p >> 6, o = p & 63;
        float acc = bias_h[o];
        #pragma unroll
        for (int i = 0; i < Dc; i++) acc += h[r][i] * w_h[i * Dc + o];
        h2tmp[pp] = acc > 0.f ? acc : 0.01f * acc;
    }
    __syncthreads();
    #pragma unroll
    for (int pp = 0; pp < 2; pp++) {
        int p = t + pp * 256;
        h[p >> 6][p & 63] = h2tmp[pp];
    }
    __syncthreads();

    {
        float a = h[w][lane], c = h[w][lane + 32];
        float s = a + c;
        #pragma unroll
        for (int o = 16; o; o >>= 1) s += __shfl_xor_sync(0xffffffffu, s, o);
        float mean = s * (1.f / 64.f);
        float da = a - mean, dc = c - mean;
        float vv = da * da + dc * dc;
        #pragma unroll
        for (int o = 16; o; o >>= 1) vv += __shfl_xor_sync(0xffffffffu, vv, o);
        float rstd = rsqrtf(vv * (1.f / 64.f) + 1e-5f);
        size_t row = row0 + w;
        float na = da * rstd * g2[lane] + b2[lane];
        float nc = dc * rstd * g2[lane + 32] + b2[lane + 32];
        out[row * Dc + lane]      = na;
        out[row * Dc + lane + 32] = nc;
        float n0 = na * na, n1 = nc * nc;
        #pragma unroll
        for (int o = 16; o; o >>= 1) {
            n0 += __shfl_xor_sync(0xffffffffu, n0, o);
            n1 += __shfl_xor_sync(0xffffffffu, n1, o);
        }
        if (lane == 0) {
            int bb = (int)(row / Lc), rr = (int)(row % Lc);
            float r0 = sqrtf(n0), r1 = sqrtf(n1);
            nrm[(bb * 2 + 0) * Lc + rr] = r0;
            nrm[(bb * 2 + 1) * Lc + rr] = r1;
            sn0[w] = r0; sn1[w] = r1;
        }
    }
    __syncthreads();
    if (t < 2) {
        float* sn = t == 0 ? sn0 : sn1;
        float m = sn[0];
        #pragma unroll
        for (int u = 1; u < 8; u++) m = fmaxf(m, sn[u]);
        int bb = (int)(row0 / Lc);
        atomicMax((int*)&mx[bb * 2 + t], __float_as_int(m));
    }
}

// ---------------------------------------------------------------------------
// Attention v6: streaming Z. j-row front-batched into registers (MLP=8),
// one scalar ull accumulator per row, hi via broadcast LDS, mh from smem.
// ---------------------------------------------------------------------------
__global__ __launch_bounds__(256, 2) void attn_kernel(
        const float* __restrict__ x,
        const float* __restrict__ mask,
        const int* __restrict__ top,
        const float* __restrict__ nrm,
        const float* __restrict__ mx,
        float* __restrict__ out) {
    __shared__ __align__(16) float hi[TI * DH];
    __shared__ float mh_s[TI];
    __shared__ float zrow[TI];
    __shared__ float wred[8 * TI];

    int t = threadIdx.x;                 // 256
    int slice = blockIdx.y;              // b*H + h
    int b = slice >> 1, hh = slice & 1;
    int i0 = blockIdx.x * TI;
    const float* xb = x + (size_t)b * Lc * Dc + hh * DH;

    for (int p = t; p < TI * DH; p += 256)
        hi[p] = xb[(size_t)(i0 + (p >> 5)) * Dc + (p & 31)];
    if (t < TI) mh_s[t] = nrm[slice * Lc + i0 + t] * mx[slice];
    __syncthreads();

    float z[TI];
    #pragma unroll
    for (int r = 0; r < TI; r++) z[r] = 0.f;

    // pass 1: streaming Z; thread = column j
    #pragma unroll 1
    for (int jj = 0; jj < Lc / 256; jj++) {
        int j = jj * 256 + t;
        const ulonglong2* hj2 = (const ulonglong2*)(xb + (size_t)j * Dc);
        // front-batched j-row load: 8 LDG.128, MLP=8
        ulonglong2 aj0 = hj2[0], aj1 = hj2[1], aj2 = hj2[2], aj3 = hj2[3];
        ulonglong2 aj4 = hj2[4], aj5 = hj2[5], aj6 = hj2[6], aj7 = hj2[7];
        float am = (1.f - mask[b * Lc + j]) * -10000.f;
        #pragma unroll
        for (int r = 0; r < TI; r++) {
            const ulonglong2* hp = (const ulonglong2*)(hi + r * DH);
            unsigned long long acc = pk2(0.f, 0.f);
            ulonglong2 h0 = hp[0], h1 = hp[1], h2 = hp[2], h3 = hp[3];
            ffma2(acc, h0.x, aj0.x); ffma2(acc, h0.y, aj0.y);
            ffma2(acc, h1.x, aj1.x); ffma2(acc, h1.y, aj1.y);
            ffma2(acc, h2.x, aj2.x); ffma2(acc, h2.y, aj2.y);
            ffma2(acc, h3.x, aj3.x); ffma2(acc, h3.y, aj3.y);
            ulonglong2 h4 = hp[4], h5 = hp[5], h6 = hp[6], h7 = hp[7];
            ffma2(acc, h4.x, aj4.x); ffma2(acc, h4.y, aj4.y);
            ffma2(acc, h5.x, aj5.x); ffma2(acc, h5.y, aj5.y);
            ffma2(acc, h6.x, aj6.x); ffma2(acc, h6.y, aj6.y);
            ffma2(acc, h7.x, aj7.x); ffma2(acc, h7.y, aj7.y);
            z[r] += __expf(upk_sum(acc) + am - mh_s[r]);
        }
    }
    // block-reduce z per row
    #pragma unroll
    for (int r = 0; r < TI; r++) {
        #pragma unroll
        for (int o = 16; o; o >>= 1) z[r] += __shfl_xor_sync(0xffffffffu, z[r], o);
    }
    if ((t & 31) == 0) {
        #pragma unroll
        for (int r = 0; r < TI; r++) wred[(t >> 5) * TI + r] = z[r];
    }
    __syncthreads();
    if (t < TI) {
        float zz = 0.f;
        #pragma unroll
        for (int w2 = 0; w2 < 8; w2++) zz += wred[w2 * TI + t];
        zrow[t] = zz;
    }
    __syncthreads();

    // pass 2: sparse top-32. Warp w: rows 2w, 2w+1. Lane = neighbor / out-dim.
    int w = t >> 5, d = t & 31;
    #pragma unroll 1
    for (int rr = 0; rr < 2; rr++) {
        int r = 2 * w + rr;
        int i = i0 + r;
        int idx = top[((size_t)(b * Lc + i)) * NNc + d];
        const ulonglong2* nj = (const ulonglong2*)(xb + (size_t)idx * Dc);
        unsigned long long acc2 = pk2(0.f, 0.f);
        #pragma unroll 1
        for (int c = 0; c < 4; c++) {
            ulonglong2 a0 = nj[2 * c], a1 = nj[2 * c + 1];
            const ulonglong2* hp = (const ulonglong2*)(hi + r * DH + c * 8);
            ulonglong2 h0 = hp[0], h1 = hp[1];
            ffma2(acc2, h0.x, a0.x);
            ffma2(acc2, h0.y, a0.y);
            ffma2(acc2, h1.x, a1.x);
            ffma2(acc2, h1.y, a1.y);
        }
        float s = upk_sum(acc2) + (1.f - mask[b * Lc + idx]) * -10000.f;
        float e = __expf(s - mh_s[r]);
        float st = e;
        #pragma unroll
        for (int o = 16; o; o >>= 1) st += __shfl_xor_sync(0xffffffffu, st, o);
        float denom = st + 1e-5f * zrow[r];
        float acc = 0.f;
        #pragma unroll
        for (int k = 0; k < 32; k++) {
            float ek = __shfl_sync(0xffffffffu, e, k);
            int   jk = __shfl_sync(0xffffffffu, idx, k);
            acc += ek * xb[(size_t)jk * Dc + d];
        }
        out[(size_t)(b * Lc + i) * Dc + hh * DH + d] = acc / denom;
    }
}

// ---------------------------------------------------------------------------
// LN over 64 + norms for next layer.
// ---------------------------------------------------------------------------
__global__ void ln_kernel(const float* __restrict__ in,
                          const float* __restrict__ g, const float* __restrict__ bt,
                          float* __restrict__ out,
                          float* __restrict__ nrm, float* __restrict__ mx) {
    __shared__ float sn0[8], sn1[8];
    int t = threadIdx.x, w = t >> 5, lane = t & 31;
    size_t row = (size_t)blockIdx.x * 8 + w;
    float a = in[row * Dc + lane], c = in[row * Dc + lane + 32];
    float s = a + c;
    #pragma unroll
    for (int o = 16; o; o >>= 1) s += __shfl_xor_sync(0xffffffffu, s, o);
    float mean = s * (1.f / 64.f);
    float da = a - mean, dc = c - mean;
    float vv = da * da + dc * dc;
    #pragma unroll
    for (int o = 16; o; o >>= 1) vv += __shfl_xor_sync(0xffffffffu, vv, o);
    float rstd = rsqrtf(vv * (1.f / 64.f) + 1e-5f);
    float na = da * rstd * g[lane] + bt[lane];
    float nc = dc * rstd * g[lane + 32] + bt[lane + 32];
    out[row * Dc + lane]      = na;
    out[row * Dc + lane + 32] = nc;
    float n0 = na * na, n1 = nc * nc;
    #pragma unroll
    for (int o = 16; o; o >>= 1) {
        n0 += __shfl_xor_sync(0xffffffffu, n0, o);
        n1 += __shfl_xor_sync(0xffffffffu, n1, o);
    }
    if (lane == 0) {
        int bb = (int)(row / Lc), rr = (int)(row % Lc);
        float r0 = sqrtf(n0), r1 = sqrtf(n1);
        nrm[(bb * 2 + 0) * Lc + rr] = r0;
        nrm[(bb * 2 + 1) * Lc + rr] = r1;
        sn0[w] = r0; sn1[w] = r1;
    }
    __syncthreads();
    if (t < 2) {
        float* sn = t == 0 ? sn0 : sn1;
        float m = sn[0];
        #pragma unroll
        for (int u = 1; u < 8; u++) m = fmaxf(m, sn[u]);
        int bb = (int)(((size_t)blockIdx.x * 8) / Lc);
        atomicMax((int*)&mx[bb * 2 + t], __float_as_int(m));
    }
}

__global__ void ln_proj_kernel(const float* __restrict__ in,
                               const float* __restrict__ g, const float* __restrict__ bt,
                               const float* __restrict__ wo, const float* __restrict__ bo,
                               float* __restrict__ y) {
    int t = threadIdx.x, w = t >> 5, lane = t & 31;
    size_t row = (size_t)blockIdx.x * 8 + w;
    float a = in[row * Dc + lane], c = in[row * Dc + lane + 32];
    float s = a + c;
    #pragma unroll
    for (int o = 16; o; o >>= 1) s += __shfl_xor_sync(0xffffffffu, s, o);
    float mean = s * (1.f / 64.f);
    float da = a - mean, dc = c - mean;
    float vv = da * da + dc * dc;
    #pragma unroll
    for (int o = 16; o; o >>= 1) vv += __shfl_xor_sync(0xffffffffu, vv, o);
    float rstd = rsqrtf(vv * (1.f / 64.f) + 1e-5f);
    float na = da * rstd * g[lane] + bt[lane];
    float nc = dc * rstd * g[lane + 32] + bt[lane + 32];
    float contrib = na * wo[lane] + nc * wo[lane + 32];
    #pragma unroll
    for (int o = 16; o; o >>= 1) contrib += __shfl_xor_sync(0xffffffffu, contrib, o);
    if (lane == 0) y[row] = contrib + bo[0];
}

// ---------------------------------------------------------------------------
extern "C" void kernel_launch(void* const* d_in, const int* in_sizes, int n_in,
                              void* d_out, int out_size) {
    const float* node  = (const float*)d_in[0];
    const float* dist  = (const float*)d_in[2];
    const float* mask  = (const float*)d_in[3];
    const float* ln_in_g = (const float*)d_in[4];
    const float* ln_in_b = (const float*)d_in[5];
    const float* w_in    = (const float*)d_in[6];
    const float* b_in    = (const float*)d_in[7];
    const float* g1      = (const float*)d_in[8];
    const float* b1      = (const float*)d_in[9];
    const float* w_h     = (const float*)d_in[10];
    const float* b_h     = (const float*)d_in[11];
    const float* g2      = (const float*)d_in[12];
    const float* b2      = (const float*)d_in[13];
    const float* a0g     = (const float*)d_in[14];
    const float* a0b     = (const float*)d_in[15];
    const float* a1g     = (const float*)d_in[16];
    const float* a1b     = (const float*)d_in[17];
    const float* w_out   = (const float*)d_in[18];
    const float* b_out   = (const float*)d_in[19];
    float* y = (float*)d_out;

    void *pxa, *pxb, *pattn, *ptop, *pnrm, *pmx;
    cudaGetSymbolAddress(&pxa, g_xa);
    cudaGetSymbolAddress(&pxb, g_xb);
    cudaGetSymbolAddress(&pattn, g_attn);
    cudaGetSymbolAddress(&ptop, g_top);
    cudaGetSymbolAddress(&pnrm, g_norm);
    cudaGetSymbolAddress(&pmx, g_maxn);
    float* xa   = (float*)pxa;
    float* xb   = (float*)pxb;
    float* attn = (float*)pattn;
    int*   topi = (int*)ptop;
    float* nrm  = (float*)pnrm;
    float* mxn  = (float*)pmx;

    cudaMemsetAsync(mxn, 0, 2 * Bc * Hc * sizeof(float));

    topk_kernel<<<Bc * Lc, 256>>>(dist, mask, topi);
    mlp_kernel<<<Bc * Lc / 8, 256>>>(node, ln_in_g, ln_in_b, w_in, b_in,
                                     g1, b1, w_h, b_h, g2, b2, xa,
                                     nrm, mxn);

    dim3 agrid(Lc / TI, Bc * Hc);
    attn_kernel<<<agrid, 256>>>(xa, mask, topi, nrm, mxn, attn);
    ln_kernel<<<Bc * Lc / 8, 256>>>(attn, a0g, a0b, xb, nrm, mxn + Bc * Hc);
    attn_kernel<<<agrid, 256>>>(xb, mask, topi, nrm, mxn + Bc * Hc, attn);
    ln_proj_kernel<<<Bc * Lc / 8, 256>>>(attn, a1g, a1b, w_out, b_out, y);
}

// round 15
// speedup vs baseline: 2.4738x; 2.4738x over previous
#include <cuda_runtime.h>
#include <cuda_bf16.h>
#include <float.h>

#define Bc   8
#define Lc   2048
#define IND  1024
#define Dc   64
#define Hc   2
#define DH   32
#define NNc  32
#define TI   8
#define CANDMAX 288

// scratch (no allocations allowed -> __device__ globals)
__device__ float g_xa[Bc * Lc * Dc];
__device__ float g_xb[Bc * Lc * Dc];
__device__ float g_attn[Bc * Lc * Dc];
__device__ int   g_top[Bc * Lc * NNc];
__device__ float g_norm[Bc * Hc * Lc];
__device__ float g_maxn[2 * Bc * Hc];   // [0..16): layer0, [16..32): layer1

// ---- packed f32x2 helpers (FFMA2) ----
__device__ __forceinline__ void ffma2(unsigned long long& d,
                                      unsigned long long a,
                                      unsigned long long b) {
    asm("fma.rn.f32x2 %0, %1, %2, %0;" : "+l"(d) : "l"(a), "l"(b));
}
__device__ __forceinline__ unsigned long long pk2(float lo, float hi) {
    unsigned long long r;
    asm("mov.b64 %0, {%1, %2};" : "=l"(r) : "f"(lo), "f"(hi));
    return r;
}
__device__ __forceinline__ float upk_sum(unsigned long long v) {
    float lo, hi;
    asm("mov.b64 {%0, %1}, %2;" : "=f"(lo), "=f"(hi) : "l"(v));
    return lo + hi;
}

// ---------------------------------------------------------------------------
// Top-32 smallest dist per row via 256-bucket histogram select (validated).
// ---------------------------------------------------------------------------
__global__ void topk_kernel(const float* __restrict__ dist,
                            const float* __restrict__ mask,
                            int* __restrict__ top) {
    __shared__ int hist[256];
    __shared__ int cum[256];
    __shared__ int wtot[8];
    __shared__ unsigned long long cand[CANDMAX];
    __shared__ int ccount;
    __shared__ int thrB;

    int row = blockIdx.x;
    int b   = row / Lc;
    int t   = threadIdx.x, w = t >> 5, lane = t & 31;
    const float* dr = dist + (size_t)row * Lc;
    const float* mr = mask + b * Lc;

    hist[t] = 0;
    if (t == 0) ccount = 0;
    __syncthreads();

    float v[8]; int bkt[8];
    #pragma unroll
    for (int q = 0; q < 8; q++) {
        int j = w * 256 + q * 32 + lane;
        float m = mr[j];
        float val = (m > 0.f) ? dr[j] : 3.0f;
        v[q] = val;
        int bb = (int)(val * 256.f);
        bb = bb < 0 ? 0 : (bb > 255 ? 255 : bb);
        bkt[q] = bb;
        atomicAdd(&hist[bb], 1);
    }
    __syncthreads();

    {
        int sc = hist[t];
        #pragma unroll
        for (int o = 1; o < 32; o <<= 1) {
            int n = __shfl_up_sync(0xffffffffu, sc, o);
            if (lane >= o) sc += n;
        }
        if (lane == 31) wtot[w] = sc;
        __syncthreads();
        int off = 0;
        #pragma unroll
        for (int k = 0; k < 8; k++) if (k < w) off += wtot[k];
        cum[t] = sc + off;
    }
    __syncthreads();
    if (cum[t] >= NNc && (t == 0 || cum[t - 1] < NNc)) thrB = t;
    __syncthreads();
    int T = thrB;

    #pragma unroll
    for (int q = 0; q < 8; q++) {
        if (bkt[q] <= T) {
            int pos = atomicAdd(&ccount, 1);
            if (pos < CANDMAX) {
                int j = w * 256 + q * 32 + lane;
                cand[pos] = ((unsigned long long)__float_as_uint(v[q]) << 32) | (unsigned)j;
            }
        }
    }
    __syncthreads();
    int C = ccount;

    if (C > CANDMAX) {
        unsigned long long k8[8];
        #pragma unroll
        for (int q = 0; q < 8; q++) {
            int j = w * 256 + q * 32 + lane;
            k8[q] = ((unsigned long long)__float_as_uint(v[q]) << 32) | (unsigned)j;
        }
        for (int k = 0; k < 32; k++) {
            unsigned long long bm = k8[0]; int bq = 0;
            #pragma unroll
            for (int q = 1; q < 8; q++) if (k8[q] < bm) { bm = k8[q]; bq = q; }
            unsigned long long rm = bm;
            #pragma unroll
            for (int o = 16; o; o >>= 1) {
                unsigned long long om = __shfl_xor_sync(0xffffffffu, rm, o);
                rm = om < rm ? om : rm;
            }
            if (bm == rm) k8[bq] = 0xffffffffffffffffull;
            if (lane == 0) cand[w * 32 + k] = rm;
        }
        __syncthreads();
        C = 256;
    }

    for (int c = t; c < C; c += 256) {
        unsigned long long my = cand[c];
        int rank = 0;
        for (int k = 0; k < C; k++) rank += (cand[k] < my);
        if (rank < NNc)
            top[(size_t)row * NNc + rank] = (int)(my & 0xffffffffu);
    }
}

// ---------------------------------------------------------------------------
// Fused front-end MLP (FFMA2 GEMM1); epilogue emits norms.
// ---------------------------------------------------------------------------
__global__ void mlp_kernel(const float* __restrict__ node,
                           const float* __restrict__ gin, const float* __restrict__ bin,
                           const float* __restrict__ w_in, const float* __restrict__ bias_in,
                           const float* __restrict__ g1, const float* __restrict__ b1,
                           const float* __restrict__ w_h, const float* __restrict__ bias_h,
                           const float* __restrict__ g2, const float* __restrict__ b2,
                           float* __restrict__ out,
                           float* __restrict__ nrm, float* __restrict__ mx) {
    __shared__ __align__(16) float xs[8][IND];
    __shared__ float red[4][8][Dc];
    __shared__ float h[8][Dc];
    __shared__ float sn0[8], sn1[8];

    int t = threadIdx.x;
    int w = t >> 5, lane = t & 31;
    size_t row0 = (size_t)blockIdx.x * 8;

    {
        size_t row = row0 + w;
        const float* xr = node + row * IND;
        float vals[IND / 32];
        float s = 0.f;
        #pragma unroll
        for (int k = 0; k < IND / 32; k++) { float v = xr[lane + 32 * k]; vals[k] = v; s += v; }
        #pragma unroll
        for (int o = 16; o; o >>= 1) s += __shfl_xor_sync(0xffffffffu, s, o);
        float mean = s * (1.f / IND);
        float vs = 0.f;
        #pragma unroll
        for (int k = 0; k < IND / 32; k++) { float d = vals[k] - mean; vs += d * d; }
        #pragma unroll
        for (int o = 16; o; o >>= 1) vs += __shfl_xor_sync(0xffffffffu, vs, o);
        float rstd = rsqrtf(vs * (1.f / IND) + 1e-5f);
        #pragma unroll
        for (int k = 0; k < IND / 32; k++) {
            int i = lane + 32 * k;
            xs[w][i] = (vals[k] - mean) * rstd * gin[i] + bin[i];
        }
    }
    __syncthreads();

    {
        int o = t & 63, quad = t >> 6;
        unsigned long long acc[8];
        #pragma unroll
        for (int r = 0; r < 8; r++) acc[r] = pk2(0.f, 0.f);
        int i0 = quad * 256;
        for (int i = i0; i < i0 + 256; i += 4) {
            unsigned long long wp0 = pk2(w_in[(i + 0) * Dc + o], w_in[(i + 1) * Dc + o]);
            unsigned long long wp1 = pk2(w_in[(i + 2) * Dc + o], w_in[(i + 3) * Dc + o]);
            #pragma unroll
            for (int r = 0; r < 8; r++) {
                ulonglong2 xv = *(const ulonglong2*)&xs[r][i];
                ffma2(acc[r], xv.x, wp0);
                ffma2(acc[r], xv.y, wp1);
            }
        }
        #pragma unroll
        for (int r = 0; r < 8; r++) red[quad][r][o] = upk_sum(acc[r]);
    }
    __syncthreads();
    for (int p = t; p < 8 * Dc; p += 256) {
        int r = p >> 6, o = p & 63;
        float v = red[0][r][o] + red[1][r][o] + red[2][r][o] + red[3][r][o] + bias_in[o];
        h[r][o] = v > 0.f ? v : 0.01f * v;
    }
    __syncthreads();

    {
        float a = h[w][lane], c = h[w][lane + 32];
        float s = a + c;
        #pragma unroll
        for (int o = 16; o; o >>= 1) s += __shfl_xor_sync(0xffffffffu, s, o);
        float mean = s * (1.f / 64.f);
        float da = a - mean, dc = c - mean;
        float vv = da * da + dc * dc;
        #pragma unroll
        for (int o = 16; o; o >>= 1) vv += __shfl_xor_sync(0xffffffffu, vv, o);
        float rstd = rsqrtf(vv * (1.f / 64.f) + 1e-5f);
        h[w][lane]      = da * rstd * g1[lane] + b1[lane];
        h[w][lane + 32] = dc * rstd * g1[lane + 32] + b1[lane + 32];
    }
    __syncthreads();

    float h2tmp[2];
    #pragma unroll
    for (int pp = 0; pp < 2; pp++) {
        int p = t + pp * 256;
        int r = p >> 6, o = p & 63;
        float acc = bias_h[o];
        #pragma unroll
        for (int i = 0; i < Dc; i++) acc += h[r][i] * w_h[i * Dc + o];
        h2tmp[pp] = acc > 0.f ? acc : 0.01f * acc;
    }
    __syncthreads();
    #pragma unroll
    for (int pp = 0; pp < 2; pp++) {
        int p = t + pp * 256;
        h[p >> 6][p & 63] = h2tmp[pp];
    }
    __syncthreads();

    {
        float a = h[w][lane], c = h[w][lane + 32];
        float s = a + c;
        #pragma unroll
        for (int o = 16; o; o >>= 1) s += __shfl_xor_sync(0xffffffffu, s, o);
        float mean = s * (1.f / 64.f);
        float da = a - mean, dc = c - mean;
        float vv = da * da + dc * dc;
        #pragma unroll
        for (int o = 16; o; o >>= 1) vv += __shfl_xor_sync(0xffffffffu, vv, o);
        float rstd = rsqrtf(vv * (1.f / 64.f) + 1e-5f);
        size_t row = row0 + w;
        float na = da * rstd * g2[lane] + b2[lane];
        float nc = dc * rstd * g2[lane + 32] + b2[lane + 32];
        out[row * Dc + lane]      = na;
        out[row * Dc + lane + 32] = nc;
        float n0 = na * na, n1 = nc * nc;
        #pragma unroll
        for (int o = 16; o; o >>= 1) {
            n0 += __shfl_xor_sync(0xffffffffu, n0, o);
            n1 += __shfl_xor_sync(0xffffffffu, n1, o);
        }
        if (lane == 0) {
            int bb = (int)(row / Lc), rr = (int)(row % Lc);
            float r0 = sqrtf(n0), r1 = sqrtf(n1);
            nrm[(bb * 2 + 0) * Lc + rr] = r0;
            nrm[(bb * 2 + 1) * Lc + rr] = r1;
            sn0[w] = r0; sn1[w] = r1;
        }
    }
    __syncthreads();
    if (t < 2) {
        float* sn = t == 0 ? sn0 : sn1;
        float m = sn[0];
        #pragma unroll
        for (int u = 1; u < 8; u++) m = fmaxf(m, sn[u]);
        int bb = (int)(row0 / Lc);
        atomicMax((int*)&mx[bb * 2 + t], __float_as_int(m));
    }
}

// ---------------------------------------------------------------------------
// Attention v7: TI=8 streaming Z. aj front-batched (8 LDG.128, MLP=8);
// memory clobber blocks LICM of the hi LDS across jj iterations; row loop
// fully unrolled with static acc[]/z[] indices. ~85 regs by construction.
// ---------------------------------------------------------------------------
__global__ __launch_bounds__(256) void attn_kernel(
        const float* __restrict__ x,
        const float* __restrict__ mask,
        const int* __restrict__ top,
        const float* __restrict__ nrm,
        const float* __restrict__ mx,
        float* __restrict__ out) {
    __shared__ __align__(16) float hi[TI * DH];
    __shared__ float mh_s[TI];
    __shared__ float zrow[TI];
    __shared__ float wred[8 * TI];

    int t = threadIdx.x;                 // 256
    int slice = blockIdx.y;              // b*H + h
    int b = slice >> 1, hh = slice & 1;
    int i0 = blockIdx.x * TI;
    const float* xb = x + (size_t)b * Lc * Dc + hh * DH;

    if (t < TI * DH)
        hi[t] = xb[(size_t)(i0 + (t >> 5)) * Dc + (t & 31)];
    if (t >= 256 - TI) {
        int r = t - (256 - TI);
        mh_s[r] = nrm[slice * Lc + i0 + r] * mx[slice];
    }
    __syncthreads();

    float z[TI];
    #pragma unroll
    for (int r = 0; r < TI; r++) z[r] = 0.f;

    // pass 1: streaming Z; thread = column j
    #pragma unroll 1
    for (int jj = 0; jj < Lc / 256; jj++) {
        int j = jj * 256 + t;
        const ulonglong2* hj2 = (const ulonglong2*)(xb + (size_t)j * Dc);
        // front-batched j-row: 8 consecutive LDG.128 (MLP=8)
        ulonglong2 aj0 = hj2[0], aj1 = hj2[1], aj2 = hj2[2], aj3 = hj2[3];
        ulonglong2 aj4 = hj2[4], aj5 = hj2[5], aj6 = hj2[6], aj7 = hj2[7];
        float am = (1.f - mask[b * Lc + j]) * -10000.f;
        asm volatile("" ::: "memory");   // block smem-LDS hoisting across jj
        unsigned long long acc[TI];
        #pragma unroll
        for (int r = 0; r < TI; r++) acc[r] = pk2(0.f, 0.f);
        #pragma unroll
        for (int r = 0; r < TI; r++) {
            const ulonglong2* hp = (const ulonglong2*)(hi + r * DH);
            ulonglong2 h0 = hp[0], h1 = hp[1], h2 = hp[2], h3 = hp[3];
            ffma2(acc[r], h0.x, aj0.x); ffma2(acc[r], h0.y, aj0.y);
            ffma2(acc[r], h1.x, aj1.x); ffma2(acc[r], h1.y, aj1.y);
            ffma2(acc[r], h2.x, aj2.x); ffma2(acc[r], h2.y, aj2.y);
            ffma2(acc[r], h3.x, aj3.x); ffma2(acc[r], h3.y, aj3.y);
            ulonglong2 h4 = hp[4], h5 = hp[5], h6 = hp[6], h7 = hp[7];
            ffma2(acc[r], h4.x, aj4.x); ffma2(acc[r], h4.y, aj4.y);
            ffma2(acc[r], h5.x, aj5.x); ffma2(acc[r], h5.y, aj5.y);
            ffma2(acc[r], h6.x, aj6.x); ffma2(acc[r], h6.y, aj6.y);
            ffma2(acc[r], h7.x, aj7.x); ffma2(acc[r], h7.y, aj7.y);
        }
        #pragma unroll
        for (int r = 0; r < TI; r++)
            z[r] += __expf(upk_sum(acc[r]) + am - mh_s[r]);
    }
    // block-reduce z per row
    #pragma unroll
    for (int r = 0; r < TI; r++) {
        #pragma unroll
        for (int o = 16; o; o >>= 1) z[r] += __shfl_xor_sync(0xffffffffu, z[r], o);
    }
    if ((t & 31) == 0) {
        #pragma unroll
        for (int r = 0; r < TI; r++) wred[(t >> 5) * TI + r] = z[r];
    }
    __syncthreads();
    if (t < TI) {
        float zz = 0.f;
        #pragma unroll
        for (int w2 = 0; w2 < 8; w2++) zz += wred[w2 * TI + t];
        zrow[t] = zz;
    }
    __syncthreads();

    // pass 2: sparse top-32. Warp w handles row w. Lane = neighbor / out-dim.
    int w = t >> 5, d = t & 31;
    {
        int r = w;
        int i = i0 + r;
        int idx = top[((size_t)(b * Lc + i)) * NNc + d];
        const ulonglong2* nj = (const ulonglong2*)(xb + (size_t)idx * Dc);
        unsigned long long acc2 = pk2(0.f, 0.f);
        #pragma unroll 1
        for (int c = 0; c < 4; c++) {
            ulonglong2 a0 = nj[2 * c], a1 = nj[2 * c + 1];
            const ulonglong2* hp = (const ulonglong2*)(hi + r * DH + c * 8);
            ulonglong2 h0 = hp[0], h1 = hp[1];
            ffma2(acc2, h0.x, a0.x);
            ffma2(acc2, h0.y, a0.y);
            ffma2(acc2, h1.x, a1.x);
            ffma2(acc2, h1.y, a1.y);
        }
        float s = upk_sum(acc2) + (1.f - mask[b * Lc + idx]) * -10000.f;
        float e = __expf(s - mh_s[r]);
        float st = e;
        #pragma unroll
        for (int o = 16; o; o >>= 1) st += __shfl_xor_sync(0xffffffffu, st, o);
        float denom = st + 1e-5f * zrow[r];
        float acc = 0.f;
        #pragma unroll
        for (int k = 0; k < 32; k++) {
            float ek = __shfl_sync(0xffffffffu, e, k);
            int   jk = __shfl_sync(0xffffffffu, idx, k);
            acc += ek * xb[(size_t)jk * Dc + d];
        }
        out[(size_t)(b * Lc + i) * Dc + hh * DH + d] = acc / denom;
    }
}

// ---------------------------------------------------------------------------
// LN over 64 + norms for next layer.
// ---------------------------------------------------------------------------
__global__ void ln_kernel(const float* __restrict__ in,
                          const float* __restrict__ g, const float* __restrict__ bt,
                          float* __restrict__ out,
                          float* __restrict__ nrm, float* __restrict__ mx) {
    __shared__ float sn0[8], sn1[8];
    int t = threadIdx.x, w = t >> 5, lane = t & 31;
    size_t row = (size_t)blockIdx.x * 8 + w;
    float a = in[row * Dc + lane], c = in[row * Dc + lane + 32];
    float s = a + c;
    #pragma unroll
    for (int o = 16; o; o >>= 1) s += __shfl_xor_sync(0xffffffffu, s, o);
    float mean = s * (1.f / 64.f);
    float da = a - mean, dc = c - mean;
    float vv = da * da + dc * dc;
    #pragma unroll
    for (int o = 16; o; o >>= 1) vv += __shfl_xor_sync(0xffffffffu, vv, o);
    float rstd = rsqrtf(vv * (1.f / 64.f) + 1e-5f);
    float na = da * rstd * g[lane] + bt[lane];
    float nc = dc * rstd * g[lane + 32] + bt[lane + 32];
    out[row * Dc + lane]      = na;
    out[row * Dc + lane + 32] = nc;
    float n0 = na * na, n1 = nc * nc;
    #pragma unroll
    for (int o = 16; o; o >>= 1) {
        n0 += __shfl_xor_sync(0xffffffffu, n0, o);
        n1 += __shfl_xor_sync(0xffffffffu, n1, o);
    }
    if (lane == 0) {
        int bb = (int)(row / Lc), rr = (int)(row % Lc);
        float r0 = sqrtf(n0), r1 = sqrtf(n1);
        nrm[(bb * 2 + 0) * Lc + rr] = r0;
        nrm[(bb * 2 + 1) * Lc + rr] = r1;
        sn0[w] = r0; sn1[w] = r1;
    }
    __syncthreads();
    if (t < 2) {
        float* sn = t == 0 ? sn0 : sn1;
        float m = sn[0];
        #pragma unroll
        for (int u = 1; u < 8; u++) m = fmaxf(m, sn[u]);
        int bb = (int)(((size_t)blockIdx.x * 8) / Lc);
        atomicMax((int*)&mx[bb * 2 + t], __float_as_int(m));
    }
}

__global__ void ln_proj_kernel(const float* __restrict__ in,
                               const float* __restrict__ g, const float* __restrict__ bt,
                               const float* __restrict__ wo, const float* __restrict__ bo,
                               float* __restrict__ y) {
    int t = threadIdx.x, w = t >> 5, lane = t & 31;
    size_t row = (size_t)blockIdx.x * 8 + w;
    float a = in[row * Dc + lane], c = in[row * Dc + lane + 32];
    float s = a + c;
    #pragma unroll
    for (int o = 16; o; o >>= 1) s += __shfl_xor_sync(0xffffffffu, s, o);
    float mean = s * (1.f / 64.f);
    float da = a - mean, dc = c - mean;
    float vv = da * da + dc * dc;
    #pragma unroll
    for (int o = 16; o; o >>= 1) vv += __shfl_xor_sync(0xffffffffu, vv, o);
    float rstd = rsqrtf(vv * (1.f / 64.f) + 1e-5f);
    float na = da * rstd * g[lane] + bt[lane];
    float nc = dc * rstd * g[lane + 32] + bt[lane + 32];
    float contrib = na * wo[lane] + nc * wo[lane + 32];
    #pragma unroll
    for (int o = 16; o; o >>= 1) contrib += __shfl_xor_sync(0xffffffffu, contrib, o);
    if (lane == 0) y[row] = contrib + bo[0];
}

// ---------------------------------------------------------------------------
extern "C" void kernel_launch(void* const* d_in, const int* in_sizes, int n_in,
                              void* d_out, int out_size) {
    const float* node  = (const float*)d_in[0];
    const float* dist  = (const float*)d_in[2];
    const float* mask  = (const float*)d_in[3];
    const float* ln_in_g = (const float*)d_in[4];
    const float* ln_in_b = (const float*)d_in[5];
    const float* w_in    = (const float*)d_in[6];
    const float* b_in    = (const float*)d_in[7];
    const float* g1      = (const float*)d_in[8];
    const float* b1      = (const float*)d_in[9];
    const float* w_h     = (const float*)d_in[10];
    const float* b_h     = (const float*)d_in[11];
    const float* g2      = (const float*)d_in[12];
    const float* b2      = (const float*)d_in[13];
    const float* a0g     = (const float*)d_in[14];
    const float* a0b     = (const float*)d_in[15];
    const float* a1g     = (const float*)d_in[16];
    const float* a1b     = (const float*)d_in[17];
    const float* w_out   = (const float*)d_in[18];
    const float* b_out   = (const float*)d_in[19];
    float* y = (float*)d_out;

    void *pxa, *pxb, *pattn, *ptop, *pnrm, *pmx;
    cudaGetSymbolAddress(&pxa, g_xa);
    cudaGetSymbolAddress(&pxb, g_xb);
    cudaGetSymbolAddress(&pattn, g_attn);
    cudaGetSymbolAddress(&ptop, g_top);
    cudaGetSymbolAddress(&pnrm, g_norm);
    cudaGetSymbolAddress(&pmx, g_maxn);
    float* xa   = (float*)pxa;
    float* xb   = (float*)pxb;
    float* attn = (float*)pattn;
    int*   topi = (int*)ptop;
    float* nrm  = (float*)pnrm;
    float* mxn  = (float*)pmx;

    cudaMemsetAsync(mxn, 0, 2 * Bc * Hc * sizeof(float));

    topk_kernel<<<Bc * Lc, 256>>>(dist, mask, topi);
    mlp_kernel<<<Bc * Lc / 8, 256>>>(node, ln_in_g, ln_in_b, w_in, b_in,
                                     g1, b1, w_h, b_h, g2, b2, xa,
                                     nrm, mxn);

    dim3 agrid(Lc / TI, Bc * Hc);
    attn_kernel<<<agrid, 256>>>(xa, mask, topi, nrm, mxn, attn);
    ln_kernel<<<Bc * Lc / 8, 256>>>(attn, a0g, a0b, xb, nrm, mxn + Bc * Hc);
    attn_kernel<<<agrid, 256>>>(xb, mask, topi, nrm, mxn + Bc * Hc, attn);
    ln_proj_kernel<<<Bc * Lc / 8, 256>>>(attn, a1g, a1b, w_out, b_out, y);
}

// round 16
// speedup vs baseline: 3.2187x; 1.3011x over previous
#include <cuda_runtime.h>
#include <cuda_bf16.h>
#include <float.h>

#define Bc   8
#define Lc   2048
#define IND  1024
#define Dc   64
#define Hc   2
#define DH   32
#define NNc  32
#define TI   16
#define CANDMAX 288

// scratch (no allocations allowed -> __device__ globals)
__device__ float g_xa[Bc * Lc * Dc];
__device__ float g_xb[Bc * Lc * Dc];
__device__ float g_attn[Bc * Lc * Dc];
__device__ int   g_top[Bc * Lc * NNc];
__device__ float g_norm[Bc * Hc * Lc];
__device__ float g_maxn[2 * Bc * Hc];   // [0..16): layer0, [16..32): layer1

// ---- packed f32x2 helpers (FFMA2) ----
__device__ __forceinline__ void ffma2(unsigned long long& d,
                                      unsigned long long a,
                                      unsigned long long b) {
    asm("fma.rn.f32x2 %0, %1, %2, %0;" : "+l"(d) : "l"(a), "l"(b));
}
__device__ __forceinline__ unsigned long long pk2(float lo, float hi) {
    unsigned long long r;
    asm("mov.b64 %0, {%1, %2};" : "=l"(r) : "f"(lo), "f"(hi));
    return r;
}
__device__ __forceinline__ float upk_sum(unsigned long long v) {
    float lo, hi;
    asm("mov.b64 {%0, %1}, %2;" : "=f"(lo), "=f"(hi) : "l"(v));
    return lo + hi;
}

// ---------------------------------------------------------------------------
// Top-32 smallest dist per row via 256-bucket histogram select (validated).
// ---------------------------------------------------------------------------
__global__ void topk_kernel(const float* __restrict__ dist,
                            const float* __restrict__ mask,
                            int* __restrict__ top) {
    __shared__ int hist[256];
    __shared__ int cum[256];
    __shared__ int wtot[8];
    __shared__ unsigned long long cand[CANDMAX];
    __shared__ int ccount;
    __shared__ int thrB;

    int row = blockIdx.x;
    int b   = row / Lc;
    int t   = threadIdx.x, w = t >> 5, lane = t & 31;
    const float* dr = dist + (size_t)row * Lc;
    const float* mr = mask + b * Lc;

    hist[t] = 0;
    if (t == 0) ccount = 0;
    __syncthreads();

    float v[8]; int bkt[8];
    #pragma unroll
    for (int q = 0; q < 8; q++) {
        int j = w * 256 + q * 32 + lane;
        float m = mr[j];
        float val = (m > 0.f) ? dr[j] : 3.0f;
        v[q] = val;
        int bb = (int)(val * 256.f);
        bb = bb < 0 ? 0 : (bb > 255 ? 255 : bb);
        bkt[q] = bb;
        atomicAdd(&hist[bb], 1);
    }
    __syncthreads();

    {
        int sc = hist[t];
        #pragma unroll
        for (int o = 1; o < 32; o <<= 1) {
            int n = __shfl_up_sync(0xffffffffu, sc, o);
            if (lane >= o) sc += n;
        }
        if (lane == 31) wtot[w] = sc;
        __syncthreads();
        int off = 0;
        #pragma unroll
        for (int k = 0; k < 8; k++) if (k < w) off += wtot[k];
        cum[t] = sc + off;
    }
    __syncthreads();
    if (cum[t] >= NNc && (t == 0 || cum[t - 1] < NNc)) thrB = t;
    __syncthreads();
    int T = thrB;

    #pragma unroll
    for (int q = 0; q < 8; q++) {
        if (bkt[q] <= T) {
            int pos = atomicAdd(&ccount, 1);
            if (pos < CANDMAX) {
                int j = w * 256 + q * 32 + lane;
                cand[pos] = ((unsigned long long)__float_as_uint(v[q]) << 32) | (unsigned)j;
            }
        }
    }
    __syncthreads();
    int C = ccount;

    if (C > CANDMAX) {
        unsigned long long k8[8];
        #pragma unroll
        for (int q = 0; q < 8; q++) {
            int j = w * 256 + q * 32 + lane;
            k8[q] = ((unsigned long long)__float_as_uint(v[q]) << 32) | (unsigned)j;
        }
        for (int k = 0; k < 32; k++) {
            unsigned long long bm = k8[0]; int bq = 0;
            #pragma unroll
            for (int q = 1; q < 8; q++) if (k8[q] < bm) { bm = k8[q]; bq = q; }
            unsigned long long rm = bm;
            #pragma unroll
            for (int o = 16; o; o >>= 1) {
                unsigned long long om = __shfl_xor_sync(0xffffffffu, rm, o);
                rm = om < rm ? om : rm;
            }
            if (bm == rm) k8[bq] = 0xffffffffffffffffull;
            if (lane == 0) cand[w * 32 + k] = rm;
        }
        __syncthreads();
        C = 256;
    }

    for (int c = t; c < C; c += 256) {
        unsigned long long my = cand[c];
        int rank = 0;
        for (int k = 0; k < C; k++) rank += (cand[k] < my);
        if (rank < NNc)
            top[(size_t)row * NNc + rank] = (int)(my & 0xffffffffu);
    }
}

// ---------------------------------------------------------------------------
// Fused front-end MLP (FFMA2 GEMM1); epilogue emits norms.
// ---------------------------------------------------------------------------
__global__ void mlp_kernel(const float* __restrict__ node,
                           const float* __restrict__ gin, const float* __restrict__ bin,
                           const float* __restrict__ w_in, const float* __restrict__ bias_in,
                           const float* __restrict__ g1, const float* __restrict__ b1,
                           const float* __restrict__ w_h, const float* __restrict__ bias_h,
                           const float* __restrict__ g2, const float* __restrict__ b2,
                           float* __restrict__ out,
                           float* __restrict__ nrm, float* __restrict__ mx) {
    __shared__ __align__(16) float xs[8][IND];
    __shared__ float red[4][8][Dc];
    __shared__ float h[8][Dc];
    __shared__ float sn0[8], sn1[8];

    int t = threadIdx.x;
    int w = t >> 5, lane = t & 31;
    size_t row0 = (size_t)blockIdx.x * 8;

    {
        size_t row = row0 + w;
        const float* xr = node + row * IND;
        float vals[IND / 32];
        float s = 0.f;
        #pragma unroll
        for (int k = 0; k < IND / 32; k++) { float v = xr[lane + 32 * k]; vals[k] = v; s += v; }
        #pragma unroll
        for (int o = 16; o; o >>= 1) s += __shfl_xor_sync(0xffffffffu, s, o);
        float mean = s * (1.f / IND);
        float vs = 0.f;
        #pragma unroll
        for (int k = 0; k < IND / 32; k++) { float d = vals[k] - mean; vs += d * d; }
        #pragma unroll
        for (int o = 16; o; o >>= 1) vs += __shfl_xor_sync(0xffffffffu, vs, o);
        float rstd = rsqrtf(vs * (1.f / IND) + 1e-5f);
        #pragma unroll
        for (int k = 0; k < IND / 32; k++) {
            int i = lane + 32 * k;
            xs[w][i] = (vals[k] - mean) * rstd * gin[i] + bin[i];
        }
    }
    __syncthreads();

    {
        int o = t & 63, quad = t >> 6;
        unsigned long long acc[8];
        #pragma unroll
        for (int r = 0; r < 8; r++) acc[r] = pk2(0.f, 0.f);
        int i0 = quad * 256;
        for (int i = i0; i < i0 + 256; i += 4) {
            unsigned long long wp0 = pk2(w_in[(i + 0) * Dc + o], w_in[(i + 1) * Dc + o]);
            unsigned long long wp1 = pk2(w_in[(i + 2) * Dc + o], w_in[(i + 3) * Dc + o]);
            #pragma unroll
            for (int r = 0; r < 8; r++) {
                ulonglong2 xv = *(const ulonglong2*)&xs[r][i];
                ffma2(acc[r], xv.x, wp0);
                ffma2(acc[r], xv.y, wp1);
            }
        }
        #pragma unroll
        for (int r = 0; r < 8; r++) red[quad][r][o] = upk_sum(acc[r]);
    }
    __syncthreads();
    for (int p = t; p < 8 * Dc; p += 256) {
        int r = p >> 6, o = p & 63;
        float v = red[0][r][o] + red[1][r][o] + red[2][r][o] + red[3][r][o] + bias_in[o];
        h[r][o] = v > 0.f ? v : 0.01f * v;
    }
    __syncthreads();

    {
        float a = h[w][lane], c = h[w][lane + 32];
        float s = a + c;
        #pragma unroll
        for (int o = 16; o; o >>= 1) s += __shfl_xor_sync(0xffffffffu, s, o);
        float mean = s * (1.f / 64.f);
        float da = a - mean, dc = c - mean;
        float vv = da * da + dc * dc;
        #pragma unroll
        for (int o = 16; o; o >>= 1) vv += __shfl_xor_sync(0xffffffffu, vv, o);
        float rstd = rsqrtf(vv * (1.f / 64.f) + 1e-5f);
        h[w][lane]      = da * rstd * g1[lane] + b1[lane];
        h[w][lane + 32] = dc * rstd * g1[lane + 32] + b1[lane + 32];
    }
    __syncthreads();

    float h2tmp[2];
    #pragma unroll
    for (int pp = 0; pp < 2; pp++) {
        int p = t + pp * 256;
        int r = p >> 6, o = p & 63;
        float acc = bias_h[o];
        #pragma unroll
        for (int i = 0; i < Dc; i++) acc += h[r][i] * w_h[i * Dc + o];
        h2tmp[pp] = acc > 0.f ? acc : 0.01f * acc;
    }
    __syncthreads();
    #pragma unroll
    for (int pp = 0; pp < 2; pp++) {
        int p = t + pp * 256;
        h[p >> 6][p & 63] = h2tmp[pp];
    }
    __syncthreads();

    {
        float a = h[w][lane], c = h[w][lane + 32];
        float s = a + c;
        #pragma unroll
        for (int o = 16; o; o >>= 1) s += __shfl_xor_sync(0xffffffffu, s, o);
        float mean = s * (1.f / 64.f);
        float da = a - mean, dc = c - mean;
        float vv = da * da + dc * dc;
        #pragma unroll
        for (int o = 16; o; o >>= 1) vv += __shfl_xor_sync(0xffffffffu, vv, o);
        float rstd = rsqrtf(vv * (1.f / 64.f) + 1e-5f);
        size_t row = row0 + w;
        float na = da * rstd * g2[lane] + b2[lane];
        float nc = dc * rstd * g2[lane + 32] + b2[lane + 32];
        out[row * Dc + lane]      = na;
        out[row * Dc + lane + 32] = nc;
        float n0 = na * na, n1 = nc * nc;
        #pragma unroll
        for (int o = 16; o; o >>= 1) {
            n0 += __shfl_xor_sync(0xffffffffu, n0, o);
            n1 += __shfl_xor_sync(0xffffffffu, n1, o);
        }
        if (lane == 0) {
            int bb = (int)(row / Lc), rr = (int)(row % Lc);
            float r0 = sqrtf(n0), r1 = sqrtf(n1);
            nrm[(bb * 2 + 0) * Lc + rr] = r0;
            nrm[(bb * 2 + 1) * Lc + rr] = r1;
            sn0[w] = r0; sn1[w] = r1;
        }
    }
    __syncthreads();
    if (t < 2) {
        float* sn = t == 0 ? sn0 : sn1;
        float m = sn[0];
        #pragma unroll
        for (int u = 1; u < 8; u++) m = fmaxf(m, sn[u]);
        int bb = (int)(row0 / Lc);
        atomicMax((int*)&mx[bb * 2 + t], __float_as_int(m));
    }
}

// ---------------------------------------------------------------------------
// Attention v8: R10 chunked streaming Z + software-pipelined chunk loads.
// Chunk c+1's two LDG.128 issue before chunk c's FFMA2 body, hiding L2
// latency under compute. hi stays in smem behind the non-unrolled chunk
// loop (LICM fence). mh read from smem at exp time (lower reg pressure).
// ---------------------------------------------------------------------------
__global__ __launch_bounds__(256, 2) void attn_kernel(
        const float* __restrict__ x,
        const float* __restrict__ mask,
        const int* __restrict__ top,
        const float* __restrict__ nrm,
        const float* __restrict__ mx,
        float* __restrict__ out) {
    __shared__ __align__(16) float hi[TI * DH];
    __shared__ float mh_s[TI];
    __shared__ float zrow[TI];
    __shared__ float wred[8 * TI];

    int t = threadIdx.x;                 // 256
    int slice = blockIdx.y;              // b*H + h
    int b = slice >> 1, hh = slice & 1;
    int i0 = blockIdx.x * TI;
    const float* xb = x + (size_t)b * Lc * Dc + hh * DH;

    for (int p = t; p < TI * DH; p += 256)
        hi[p] = xb[(size_t)(i0 + (p >> 5)) * Dc + (p & 31)];
    if (t < TI) mh_s[t] = nrm[slice * Lc + i0 + t] * mx[slice];
    __syncthreads();

    float z[TI];
    #pragma unroll
    for (int r = 0; r < TI; r++) z[r] = 0.f;

    // pass 1: streaming Z; thread = column j; chunk loop software-pipelined
    #pragma unroll 1
    for (int jj = 0; jj < Lc / 256; jj++) {
        int j = jj * 256 + t;
        const ulonglong2* hj2 = (const ulonglong2*)(xb + (size_t)j * Dc);
        float am = (1.f - mask[b * Lc + j]) * -10000.f;
        unsigned long long acc[TI];
        #pragma unroll
        for (int r = 0; r < TI; r++) acc[r] = pk2(0.f, 0.f);
        ulonglong2 ca = hj2[0], cb = hj2[1];        // prefetch chunk 0
        #pragma unroll 1
        for (int c = 0; c < 4; c++) {
            ulonglong2 na = ca, nb = cb;
            if (c < 3) { na = hj2[2 * c + 2]; nb = hj2[2 * c + 3]; }  // prefetch next
            #pragma unroll
            for (int r = 0; r < TI; r++) {
                const ulonglong2* hp = (const ulonglong2*)(hi + r * DH + c * 8);
                ulonglong2 h0 = hp[0], h1 = hp[1];
                ffma2(acc[r], h0.x, ca.x);
                ffma2(acc[r], h0.y, ca.y);
                ffma2(acc[r], h1.x, cb.x);
                ffma2(acc[r], h1.y, cb.y);
            }
            ca = na; cb = nb;
        }
        #pragma unroll
        for (int r = 0; r < TI; r++)
            z[r] += __expf(upk_sum(acc[r]) + am - mh_s[r]);
    }
    // block-reduce z per row
    #pragma unroll
    for (int r = 0; r < TI; r++) {
        #pragma unroll
        for (int o = 16; o; o >>= 1) z[r] += __shfl_xor_sync(0xffffffffu, z[r], o);
    }
    if ((t & 31) == 0) {
        #pragma unroll
        for (int r = 0; r < TI; r++) wred[(t >> 5) * TI + r] = z[r];
    }
    __syncthreads();
    if (t < TI) {
        float zz = 0.f;
        #pragma unroll
        for (int w2 = 0; w2 < 8; w2++) zz += wred[w2 * TI + t];
        zrow[t] = zz;
    }
    __syncthreads();

    // pass 2: sparse top-32. Warp w: rows 2w, 2w+1. Lane = neighbor / out-dim.
    int w = t >> 5, d = t & 31;
    #pragma unroll 1
    for (int rr = 0; rr < 2; rr++) {
        int r = 2 * w + rr;
        int i = i0 + r;
        int idx = top[((size_t)(b * Lc + i)) * NNc + d];
        const ulonglong2* nj = (const ulonglong2*)(xb + (size_t)idx * Dc);
        unsigned long long acc2 = pk2(0.f, 0.f);
        #pragma unroll 1
        for (int c = 0; c < 4; c++) {
            ulonglong2 a0 = nj[2 * c], a1 = nj[2 * c + 1];
            const ulonglong2* hp = (const ulonglong2*)(hi + r * DH + c * 8);
            ulonglong2 h0 = hp[0], h1 = hp[1];
            ffma2(acc2, h0.x, a0.x);
            ffma2(acc2, h0.y, a0.y);
            ffma2(acc2, h1.x, a1.x);
            ffma2(acc2, h1.y, a1.y);
        }
        float s = upk_sum(acc2) + (1.f - mask[b * Lc + idx]) * -10000.f;
        float e = __expf(s - mh_s[r]);
        float st = e;
        #pragma unroll
        for (int o = 16; o; o >>= 1) st += __shfl_xor_sync(0xffffffffu, st, o);
        float denom = st + 1e-5f * zrow[r];
        float acc = 0.f;
        #pragma unroll
        for (int k = 0; k < 32; k++) {
            float ek = __shfl_sync(0xffffffffu, e, k);
            int   jk = __shfl_sync(0xffffffffu, idx, k);
            acc += ek * xb[(size_t)jk * Dc + d];
        }
        out[(size_t)(b * Lc + i) * Dc + hh * DH + d] = acc / denom;
    }
}

// ---------------------------------------------------------------------------
// LN over 64 + norms for next layer.
// ---------------------------------------------------------------------------
__global__ void ln_kernel(const float* __restrict__ in,
                          const float* __restrict__ g, const float* __restrict__ bt,
                          float* __restrict__ out,
                          float* __restrict__ nrm, float* __restrict__ mx) {
    __shared__ float sn0[8], sn1[8];
    int t = threadIdx.x, w = t >> 5, lane = t & 31;
    size_t row = (size_t)blockIdx.x * 8 + w;
    float a = in[row * Dc + lane], c = in[row * Dc + lane + 32];
    float s = a + c;
    #pragma unroll
    for (int o = 16; o; o >>= 1) s += __shfl_xor_sync(0xffffffffu, s, o);
    float mean = s * (1.f / 64.f);
    float da = a - mean, dc = c - mean;
    float vv = da * da + dc * dc;
    #pragma unroll
    for (int o = 16; o; o >>= 1) vv += __shfl_xor_sync(0xffffffffu, vv, o);
    float rstd = rsqrtf(vv * (1.f / 64.f) + 1e-5f);
    float na = da * rstd * g[lane] + bt[lane];
    float nc = dc * rstd * g[lane + 32] + bt[lane + 32];
    out[row * Dc + lane]      = na;
    out[row * Dc + lane + 32] = nc;
    float n0 = na * na, n1 = nc * nc;
    #pragma unroll
    for (int o = 16; o; o >>= 1) {
        n0 += __shfl_xor_sync(0xffffffffu, n0, o);
        n1 += __shfl_xor_sync(0xffffffffu, n1, o);
    }
    if (lane == 0) {
        int bb = (int)(row / Lc), rr = (int)(row % Lc);
        float r0 = sqrtf(n0), r1 = sqrtf(n1);
        nrm[(bb * 2 + 0) * Lc + rr] = r0;
        nrm[(bb * 2 + 1) * Lc + rr] = r1;
        sn0[w] = r0; sn1[w] = r1;
    }
    __syncthreads();
    if (t < 2) {
        float* sn = t == 0 ? sn0 : sn1;
        float m = sn[0];
        #pragma unroll
        for (int u = 1; u < 8; u++) m = fmaxf(m, sn[u]);
        int bb = (int)(((size_t)blockIdx.x * 8) / Lc);
        atomicMax((int*)&mx[bb * 2 + t], __float_as_int(m));
    }
}

__global__ void ln_proj_kernel(const float* __restrict__ in,
                               const float* __restrict__ g, const float* __restrict__ bt,
                               const float* __restrict__ wo, const float* __restrict__ bo,
                               float* __restrict__ y) {
    int t = threadIdx.x, w = t >> 5, lane = t & 31;
    size_t row = (size_t)blockIdx.x * 8 + w;
    float a = in[row * Dc + lane], c = in[row * Dc + lane + 32];
    float s = a + c;
    #pragma unroll
    for (int o = 16; o; o >>= 1) s += __shfl_xor_sync(0xffffffffu, s, o);
    float mean = s * (1.f / 64.f);
    float da = a - mean, dc = c - mean;
    float vv = da * da + dc * dc;
    #pragma unroll
    for (int o = 16; o; o >>= 1) vv += __shfl_xor_sync(0xffffffffu, vv, o);
    float rstd = rsqrtf(vv * (1.f / 64.f) + 1e-5f);
    float na = da * rstd * g[lane] + bt[lane];
    float nc = dc * rstd * g[lane + 32] + bt[lane + 32];
    float contrib = na * wo[lane] + nc * wo[lane + 32];
    #pragma unroll
    for (int o = 16; o; o >>= 1) contrib += __shfl_xor_sync(0xffffffffu, contrib, o);
    if (lane == 0) y[row] = contrib + bo[0];
}

// ---------------------------------------------------------------------------
extern "C" void kernel_launch(void* const* d_in, const int* in_sizes, int n_in,
                              void* d_out, int out_size) {
    const float* node  = (const float*)d_in[0];
    const float* dist  = (const float*)d_in[2];
    const float* mask  = (const float*)d_in[3];
    const float* ln_in_g = (const float*)d_in[4];
    const float* ln_in_b = (const float*)d_in[5];
    const float* w_in    = (const float*)d_in[6];
    const float* b_in    = (const float*)d_in[7];
    const float* g1      = (const float*)d_in[8];
    const float* b1      = (const float*)d_in[9];
    const float* w_h     = (const float*)d_in[10];
    const float* b_h     = (const float*)d_in[11];
    const float* g2      = (const float*)d_in[12];
    const float* b2      = (const float*)d_in[13];
    const float* a0g     = (const float*)d_in[14];
    const float* a0b     = (const float*)d_in[15];
    const float* a1g     = (const float*)d_in[16];
    const float* a1b     = (const float*)d_in[17];
    const float* w_out   = (const float*)d_in[18];
    const float* b_out   = (const float*)d_in[19];
    float* y = (float*)d_out;

    void *pxa, *pxb, *pattn, *ptop, *pnrm, *pmx;
    cudaGetSymbolAddress(&pxa, g_xa);
    cudaGetSymbolAddress(&pxb, g_xb);
    cudaGetSymbolAddress(&pattn, g_attn);
    cudaGetSymbolAddress(&ptop, g_top);
    cudaGetSymbolAddress(&pnrm, g_norm);
    cudaGetSymbolAddress(&pmx, g_maxn);
    float* xa   = (float*)pxa;
    float* xb   = (float*)pxb;
    float* attn = (float*)pattn;
    int*   topi = (int*)ptop;
    float* nrm  = (float*)pnrm;
    float* mxn  = (float*)pmx;

    cudaMemsetAsync(mxn, 0, 2 * Bc * Hc * sizeof(float));

    topk_kernel<<<Bc * Lc, 256>>>(dist, mask, topi);
    mlp_kernel<<<Bc * Lc / 8, 256>>>(node, ln_in_g, ln_in_b, w_in, b_in,
                                     g1, b1, w_h, b_h, g2, b2, xa,
                                     nrm, mxn);

    dim3 agrid(Lc / TI, Bc * Hc);
    attn_kernel<<<agrid, 256>>>(xa, mask, topi, nrm, mxn, attn);
    ln_kernel<<<Bc * Lc / 8, 256>>>(attn, a0g, a0b, xb, nrm, mxn + Bc * Hc);
    attn_kernel<<<agrid, 256>>>(xb, mask, topi, nrm, mxn + Bc * Hc, attn);
    ln_proj_kernel<<<Bc * Lc / 8, 256>>>(attn, a1g, a1b, w_out, b_out, y);
}